// round 14
// baseline (speedup 1.0000x reference)
#include <cuda_runtime.h>

#define N_NODES 50000
#define N_EDGES 800000
#define IN_CH   64
#define HID     128
#define LAST_HID 256
#define CAP     96          // per-node adjacency capacity; P(Poisson(16) > 96) ~ 1e-40
#define FC1_SPLIT 4

typedef unsigned long long u64;

// ---------------- scratch (static device arrays; no allocation) ----------------
__device__ __align__(16) float g_agg[N_NODES * IN_CH];
__device__ int   g_cnt[N_NODES];                 // degree counters (atomic cursors)
__device__ int   g_slots[N_NODES * CAP];         // bucketed adjacency: src per slot
__device__ float g_s[N_NODES];
__device__ float g_t[N_NODES];
__device__ __align__(16) float g_v[N_NODES];
__device__ float g_z[LAST_HID];
__device__ int   g_is64;

// ---------------- f32x2 helpers ----------------
__device__ __forceinline__ void fma2(u64& acc, u64 a, u64 b) {
    asm("fma.rn.f32x2 %0, %1, %2, %0;" : "+l"(acc) : "l"(a), "l"(b));
}
__device__ __forceinline__ float2 unpack2(u64 v) {
    float2 r; asm("mov.b64 {%0, %1}, %2;" : "=f"(r.x), "=f"(r.y) : "l"(v)); return r;
}

// ---------------- edge accessors ----------------
__device__ __forceinline__ int edge_at(const void* ei, int flat_idx, int is64) {
    if (is64) return (int)reinterpret_cast<const long long*>(ei)[flat_idx];
    return reinterpret_cast<const int*>(ei)[flat_idx];
}

// ---------------- K0: zero counters + seed z + detect dtype ----------------
__global__ void k_init(const int* __restrict__ ei32, const float* __restrict__ fc1b) {
    int i = blockIdx.x * blockDim.x + threadIdx.x;
    int stride = gridDim.x * blockDim.x;
    for (int j = i; j < N_NODES; j += stride) g_cnt[j] = 0;
    if (i < LAST_HID) g_z[i] = fc1b[i];
    if (i == 0) {
        int is64 = 1;
        for (int k = 0; k < 256; k++) {
            int idx = 2 * (k * 3000) + 1;      // odd int32 words, < 1.6M
            if (ei32[idx] != 0) { is64 = 0; break; }
        }
        g_is64 = is64;
    }
}

// ---------------- K1: single-pass bucket fill (adjacency + degree) ----------------
__global__ __launch_bounds__(256) void k_fill(const void* __restrict__ ei) {
    int e = blockIdx.x * blockDim.x + threadIdx.x;
    if (e >= N_EDGES) return;
    int is64 = g_is64;
    int src = edge_at(ei, e, is64);
    int dst = edge_at(ei, N_EDGES + e, is64);
    if ((unsigned)dst >= N_NODES || (unsigned)src >= N_NODES) return;
    int pos = atomicAdd(&g_cnt[dst], 1);
    if (pos < CAP) g_slots[dst * CAP + pos] = src;
}

// ---------------- K2: gather-aggregate x rows (16 threads/node, float4) ----------------
__global__ __launch_bounds__(256) void k_gather1(const float* __restrict__ x) {
    int t = blockIdx.x * blockDim.x + threadIdx.x;
    int node = t >> 4;
    if (node >= N_NODES) return;
    int lane = t & 15;
    int deg = g_cnt[node];
    int n = min(deg, CAP);
    const int* sl = g_slots + node * CAP;
    const float4* xp = reinterpret_cast<const float4*>(x);
    float4 accA = make_float4(0.f, 0.f, 0.f, 0.f);
    float4 accB = make_float4(0.f, 0.f, 0.f, 0.f);
    int e = 0;
    for (; e + 2 <= n; e += 2) {
        int s0 = sl[e];
        int s1 = sl[e + 1];
        float4 a = xp[s0 * 16 + lane];
        float4 b = xp[s1 * 16 + lane];
        accA.x += a.x; accA.y += a.y; accA.z += a.z; accA.w += a.w;
        accB.x += b.x; accB.y += b.y; accB.z += b.z; accB.w += b.w;
    }
    if (e < n) {
        int s0 = sl[e];
        float4 a = xp[s0 * 16 + lane];
        accA.x += a.x; accA.y += a.y; accA.z += a.z; accA.w += a.w;
    }
    accA.x += accB.x; accA.y += accB.y; accA.z += accB.z; accA.w += accB.w;
    reinterpret_cast<float4*>(g_agg)[node * 16 + lane] = accA;
}

// ---------------- K3: persistent register-tiled layer1 GEMM + relu + rank-1 pre-dots ----------------
// Block tile: 64 nodes x 128 outputs; thread = 4 nodes x 8 outputs (strided j).
// A = [agg/deg | x] (K=128), W = [W1l | W1r]; k-chunked (32) through smem with
// register prefetch of the next chunk overlapping compute of the current one.
#define ROWSTR 36
#define NTILE  64
#define NBLK   296
#define NTILES ((N_NODES + NTILE - 1) / NTILE)
__global__ __launch_bounds__(256, 2) void k_layer1(const float* __restrict__ x,
                                                   const float* __restrict__ W1l,
                                                   const float* __restrict__ b1,
                                                   const float* __restrict__ W1r,
                                                   const float* __restrict__ W2l,
                                                   const float* __restrict__ W2r) {
    __shared__ __align__(16) float sA[NTILE * ROWSTR];   // 9.2 KB
    __shared__ __align__(16) float sW[128 * ROWSTR];     // 18 KB
    __shared__ float sb[HID], s2l[HID], s2r[HID], sInv[NTILE];

    int tid = threadIdx.x;
    int jgrp = tid & 15;        // output group: j = jgrp + 16*jj
    int rgrp = tid >> 4;        // node group (0..15): rows rgrp*4 .. rgrp*4+3
    int rowA = tid >> 3;        // staging row for A/W quad loads
    int qA   = tid & 7;

    if (tid < 128) { sb[tid] = b1[tid]; s2l[tid] = W2l[tid]; s2r[tid] = W2r[tid]; }

    const float4* agg4 = reinterpret_cast<const float4*>(g_agg);
    const float4* x4   = reinterpret_cast<const float4*>(x);
    const float4* wl4  = reinterpret_cast<const float4*>(W1l);
    const float4* wr4  = reinterpret_cast<const float4*>(W1r);

    for (int tile = blockIdx.x; tile < NTILES; tile += NBLK) {
        int nb = tile * NTILE;

        // sInv for this tile (previous tile's compute finished at its last sync)
        if (tid < NTILE) {
            int node = nb + tid;
            sInv[tid] = (node < N_NODES) ? 1.0f / fmaxf((float)g_cnt[node], 1.0f) : 0.f;
        }

        u64 acc[32];
#pragma unroll
        for (int q = 0; q < 32; q++) acc[q] = 0ull;

        float4 pa[2], pw[4];
        // prefetch chunk 0
        {
#pragma unroll
            for (int it = 0; it < 2; it++) {
                int idx = tid + it * 256, row = idx >> 3, q = idx & 7;
                int node = nb + row;
                pa[it] = (node < N_NODES) ? agg4[node * 16 + q]
                                          : make_float4(0.f, 0.f, 0.f, 0.f);
            }
#pragma unroll
            for (int it = 0; it < 4; it++) {
                int idx = tid + it * 256, row = idx >> 3, q = idx & 7;
                pw[it] = wl4[row * 16 + q];
            }
        }

        for (int c = 0; c < 4; c++) {
            __syncthreads();   // prev chunk's compute done (and sInv visible at c=0)
            // store staged chunk c
#pragma unroll
            for (int it = 0; it < 2; it++) {
                int idx = tid + it * 256, row = idx >> 3, q = idx & 7;
                float4 av = pa[it];
                if (c < 2) {
                    float iv = sInv[row];
                    av.x *= iv; av.y *= iv; av.z *= iv; av.w *= iv;
                }
                *reinterpret_cast<float4*>(sA + row * ROWSTR + q * 4) = av;
            }
#pragma unroll
            for (int it = 0; it < 4; it++) {
                int idx = tid + it * 256, row = idx >> 3, q = idx & 7;
                *reinterpret_cast<float4*>(sW + row * ROWSTR + q * 4) = pw[it];
            }
            __syncthreads();
            // prefetch chunk c+1 (overlaps with compute below)
            if (c < 3) {
                int cn = c + 1;
#pragma unroll
                for (int it = 0; it < 2; it++) {
                    int idx = tid + it * 256, row = idx >> 3, q = idx & 7;
                    int node = nb + row;
                    float4 av = make_float4(0.f, 0.f, 0.f, 0.f);
                    if (node < N_NODES)
                        av = (cn < 2) ? agg4[node * 16 + cn * 8 + q]
                                      : x4[node * 16 + (cn - 2) * 8 + q];
                    pa[it] = av;
                }
#pragma unroll
                for (int it = 0; it < 4; it++) {
                    int idx = tid + it * 256, row = idx >> 3, q = idx & 7;
                    pw[it] = (cn < 2) ? wl4[row * 16 + cn * 8 + q]
                                      : wr4[row * 16 + (cn - 2) * 8 + q];
                }
            }

            // compute chunk c
#pragma unroll
            for (int kq = 0; kq < 8; kq++) {
                u64 ar[4][2];
#pragma unroll
                for (int r = 0; r < 4; r++) {
                    ulonglong2 av = *reinterpret_cast<const ulonglong2*>(
                        sA + (rgrp * 4 + r) * ROWSTR + kq * 4);
                    ar[r][0] = av.x; ar[r][1] = av.y;
                }
#pragma unroll
                for (int jj = 0; jj < 8; jj++) {
                    int j = jgrp + 16 * jj;
                    ulonglong2 wv = *reinterpret_cast<const ulonglong2*>(
                        sW + j * ROWSTR + kq * 4);
#pragma unroll
                    for (int r = 0; r < 4; r++) {
                        fma2(acc[r * 8 + jj], ar[r][0], wv.x);
                        fma2(acc[r * 8 + jj], ar[r][1], wv.y);
                    }
                }
            }
        }

        // epilogue: h = relu(dot + b); fold into rank-1 scalars; shfl-reduce 16 lanes
#pragma unroll
        for (int r = 0; r < 4; r++) {
            float sp = 0.f, tp = 0.f;
#pragma unroll
            for (int jj = 0; jj < 8; jj++) {
                int j = jgrp + 16 * jj;
                float2 f = unpack2(acc[r * 8 + jj]);
                float h = fmaxf(f.x + f.y + sb[j], 0.f);
                sp = fmaf(h, s2l[j], sp);
                tp = fmaf(h, s2r[j], tp);
            }
#pragma unroll
            for (int m = 1; m < 16; m <<= 1) {
                sp += __shfl_xor_sync(0xffffffffu, sp, m);
                tp += __shfl_xor_sync(0xffffffffu, tp, m);
            }
            if (jgrp == 0) {
                int node = nb + rgrp * 4 + r;
                if (node < N_NODES) { g_s[node] = sp; g_t[node] = tp; }
            }
        }
        __syncthreads();   // epilogue/sInv safety before next tile overwrites
    }
}

// ---------------- K4: layer-2 gather + v epilogue ----------------
__global__ __launch_bounds__(256) void k_gather2v(const float* __restrict__ b2l) {
    int i = blockIdx.x * blockDim.x + threadIdx.x;
    if (i >= N_NODES) return;
    int deg = g_cnt[i];
    int n = min(deg, CAP);
    const int* sl = g_slots + i * CAP;
    float acc = 0.f;
    for (int e = 0; e < n; e++) acc += g_s[sl[e]];
    float inv = 1.0f / fmaxf((float)deg, 1.0f);
    g_v[i] = fmaxf(fmaf(acc, inv, b2l[0] + g_t[i]), 0.f);
}

// ---------------- K5: z += partial(fc1_W @ v), split-K ----------------
__global__ __launch_bounds__(256) void k_fc1(const float* __restrict__ fc1W) {
    int r     = blockIdx.x & (LAST_HID - 1);
    int split = blockIdx.x >> 8;                     // 0..FC1_SPLIT-1
    const int chunk4 = (N_NODES / 4) / FC1_SPLIT;    // 3125 float4s
    int base = split * chunk4;
    const float4* wp = reinterpret_cast<const float4*>(fc1W + (size_t)r * N_NODES) + base;
    const float4* vp = reinterpret_cast<const float4*>(g_v) + base;
    float acc = 0.f;
    for (int idx = threadIdx.x; idx < chunk4; idx += 256) {
        float4 w = wp[idx];
        float4 v = vp[idx];
        acc = fmaf(w.x, v.x, acc);
        acc = fmaf(w.y, v.y, acc);
        acc = fmaf(w.z, v.z, acc);
        acc = fmaf(w.w, v.w, acc);
    }
    __shared__ float red[256];
    red[threadIdx.x] = acc;
    __syncthreads();
#pragma unroll
    for (int off = 128; off > 0; off >>= 1) {
        if (threadIdx.x < off) red[threadIdx.x] += red[threadIdx.x + off];
        __syncthreads();
    }
    if (threadIdx.x == 0) atomicAdd(&g_z[r], red[0]);
}

// ---------------- K6: pred ----------------
__global__ __launch_bounds__(256) void k_final(const float* __restrict__ fc2W,
                                               const float* __restrict__ fc2b,
                                               float* __restrict__ out) {
    __shared__ float red[256];
    int tid = threadIdx.x;
    red[tid] = fc2W[tid] * g_z[tid];
    __syncthreads();
#pragma unroll
    for (int off = 128; off > 0; off >>= 1) {
        if (tid < off) red[tid] += red[tid + off];
        __syncthreads();
    }
    if (tid == 0) out[0] = red[0] + fc2b[0];
}

// ---------------- launch ----------------
extern "C" void kernel_launch(void* const* d_in, const int* in_sizes, int n_in,
                              void* d_out, int out_size) {
    const float* x    = (const float*)d_in[0];
    const void*  ei   = d_in[1];
    const float* W1l  = (const float*)d_in[2];
    const float* b1l  = (const float*)d_in[3];
    const float* W1r  = (const float*)d_in[4];
    const float* W2l  = (const float*)d_in[5];
    const float* b2l  = (const float*)d_in[6];
    const float* W2r  = (const float*)d_in[7];
    const float* fc1W = (const float*)d_in[8];
    const float* fc1b = (const float*)d_in[9];
    const float* fc2W = (const float*)d_in[10];
    const float* fc2b = (const float*)d_in[11];
    float* out = (float*)d_out;

    k_init<<<256, 256>>>((const int*)ei, fc1b);
    k_fill<<<(N_EDGES + 255) / 256, 256>>>(ei);
    k_gather1<<<(N_NODES * 16 + 255) / 256, 256>>>(x);
    k_layer1<<<NBLK, 256>>>(x, W1l, b1l, W1r, W2l, W2r);
    k_gather2v<<<(N_NODES + 255) / 256, 256>>>(b2l);
    k_fc1<<<LAST_HID * FC1_SPLIT, 256>>>(fc1W);
    k_final<<<1, 256>>>(fc2W, fc2b, out);
}

// round 17
// speedup vs baseline: 1.1313x; 1.1313x over previous
#include <cuda_runtime.h>
#include <cstdint>

#define N_NODES 50000
#define N_EDGES 800000
#define IN_CH   64
#define HID     128
#define LAST_HID 256
#define CAP     96
#define FC1_SPLIT 4

// ---------------- scratch ----------------
__device__ __align__(16) float g_agg[N_NODES * IN_CH];
__device__ int   g_cnt[N_NODES];
__device__ int   g_slots[N_NODES * CAP];
__device__ float g_s[N_NODES];
__device__ float g_t[N_NODES];
__device__ __align__(16) float g_v[N_NODES];
__device__ float g_z[LAST_HID];
__device__ int   g_is64;

// ---------------- helpers ----------------
__device__ __forceinline__ uint32_t f2tf32(float f) {
    uint32_t r; asm("cvt.rna.tf32.f32 %0, %1;" : "=r"(r) : "f"(f)); return r;
}
#define MMA_TF32(C, a0, a1, a2, a3, b0, b1)                                   \
    asm volatile("mma.sync.aligned.m16n8k8.row.col.f32.tf32.tf32.f32 "        \
                 "{%0,%1,%2,%3}, {%4,%5,%6,%7}, {%8,%9}, {%0,%1,%2,%3};"      \
                 : "+f"(C[0]), "+f"(C[1]), "+f"(C[2]), "+f"(C[3])             \
                 : "r"(a0), "r"(a1), "r"(a2), "r"(a3), "r"(b0), "r"(b1))

__device__ __forceinline__ int edge_at(const void* ei, int idx, int is64) {
    if (is64) return (int)reinterpret_cast<const long long*>(ei)[idx];
    return reinterpret_cast<const int*>(ei)[idx];
}

// ---------------- K0 ----------------
__global__ void k_init(const int* __restrict__ ei32, const float* __restrict__ fc1b) {
    int i = blockIdx.x * blockDim.x + threadIdx.x;
    int stride = gridDim.x * blockDim.x;
    for (int j = i; j < N_NODES; j += stride) g_cnt[j] = 0;
    if (i < LAST_HID) g_z[i] = fc1b[i];
    if (i == 0) {
        int is64 = 1;
        for (int k = 0; k < 256; k++) {
            int idx = 2 * (k * 3000) + 1;
            if (ei32[idx] != 0) { is64 = 0; break; }
        }
        g_is64 = is64;
    }
}

// ---------------- K1: bucket fill ----------------
__global__ __launch_bounds__(256) void k_fill(const void* __restrict__ ei) {
    int e = blockIdx.x * blockDim.x + threadIdx.x;
    if (e >= N_EDGES) return;
    int is64 = g_is64;
    int src = edge_at(ei, e, is64);
    int dst = edge_at(ei, N_EDGES + e, is64);
    if ((unsigned)dst >= N_NODES || (unsigned)src >= N_NODES) return;
    int pos = atomicAdd(&g_cnt[dst], 1);
    if (pos < CAP) g_slots[dst * CAP + pos] = src;
}

// ---------------- K2: gather ----------------
__global__ __launch_bounds__(256) void k_gather1(const float* __restrict__ x) {
    int t = blockIdx.x * blockDim.x + threadIdx.x;
    int node = t >> 4;
    if (node >= N_NODES) return;
    int lane = t & 15;
    int deg = g_cnt[node];
    int n = min(deg, CAP);
    const int* sl = g_slots + node * CAP;
    const float4* xp = reinterpret_cast<const float4*>(x);
    float4 accA = make_float4(0.f, 0.f, 0.f, 0.f);
    float4 accB = make_float4(0.f, 0.f, 0.f, 0.f);
    int e = 0;
    for (; e + 2 <= n; e += 2) {
        int s0 = sl[e], s1 = sl[e + 1];
        float4 a = xp[s0 * 16 + lane];
        float4 b = xp[s1 * 16 + lane];
        accA.x += a.x; accA.y += a.y; accA.z += a.z; accA.w += a.w;
        accB.x += b.x; accB.y += b.y; accB.z += b.z; accB.w += b.w;
    }
    if (e < n) {
        int s0 = sl[e];
        float4 a = xp[s0 * 16 + lane];
        accA.x += a.x; accA.y += a.y; accA.z += a.z; accA.w += a.w;
    }
    accA.x += accB.x; accA.y += accB.y; accA.z += accB.z; accA.w += accB.w;
    reinterpret_cast<float4*>(g_agg)[node * 16 + lane] = accA;
}

// ---------------- K3: mma.sync TF32 layer1 (3x split) + relu + rank-1 pre-dots ----------------
// Block tile M=128 nodes x N=128 outputs, K=128 in 8 chunks of 16.
// Warp tile m32 x n64 (warp grid 4x2). hi/lo tf32 interleaved as uint2 in smem.
// Strides of 20 u64/row give conflict-free (4g+t) fragment access.
#define KSTR 20
#define NTILES_MMA ((N_NODES + 127) / 128)
__global__ __launch_bounds__(256) void k_layer1(const float* __restrict__ x,
                                                const float* __restrict__ W1l,
                                                const float* __restrict__ b1,
                                                const float* __restrict__ W1r,
                                                const float* __restrict__ W2l,
                                                const float* __restrict__ W2r) {
    __shared__ __align__(16) uint2 sA[128 * KSTR];   // 20.5 KB
    __shared__ __align__(16) uint2 sW[128 * KSTR];   // 20.5 KB
    __shared__ float sS[HID], sT[HID], sb[HID], s2l[HID], s2r[HID];

    int tid = threadIdx.x;
    int lane = tid & 31, wid = tid >> 5;
    int g = lane >> 2, tg = lane & 3;
    int wm = (wid & 3) * 32;    // warp m base
    int wn = (wid >> 2) * 64;   // warp n base
    int nb = blockIdx.x * 128;

    if (tid < HID) {
        sS[tid] = 0.f; sT[tid] = 0.f;
        sb[tid] = b1[tid]; s2l[tid] = W2l[tid]; s2r[tid] = W2r[tid];
    }

    float c[2][8][4];
#pragma unroll
    for (int a = 0; a < 2; a++)
#pragma unroll
        for (int b = 0; b < 8; b++)
#pragma unroll
            for (int q = 0; q < 4; q++) c[a][b][q] = 0.f;

    const float4* agg4 = reinterpret_cast<const float4*>(g_agg);
    const float4* x4   = reinterpret_cast<const float4*>(x);
    const float4* wl4  = reinterpret_cast<const float4*>(W1l);
    const float4* wr4  = reinterpret_cast<const float4*>(W1r);

    int mrow  = tid >> 1;            // staging row (node row for A, j row for W)
    int khalf = (tid & 1) * 8;       // k offset within 16-chunk
    int node  = nb + mrow;
    float inv = (node < N_NODES) ? 1.0f / fmaxf((float)g_cnt[node], 1.0f) : 0.f;

    for (int ch = 0; ch < 8; ch++) {
        __syncthreads();    // previous chunk's fragment reads complete
#pragma unroll
        for (int h = 0; h < 2; h++) {
            int gk = ch * 16 + khalf + h * 4;     // global k of this float4
            // ---- A ----
            float4 v = make_float4(0.f, 0.f, 0.f, 0.f);
            if (node < N_NODES) {
                if (gk < 64) {
                    v = agg4[node * 16 + (gk >> 2)];
                    v.x *= inv; v.y *= inv; v.z *= inv; v.w *= inv;
                } else {
                    v = x4[node * 16 + ((gk - 64) >> 2)];
                }
            }
            uint32_t hx = f2tf32(v.x), hy = f2tf32(v.y), hz = f2tf32(v.z), hw = f2tf32(v.w);
            uint4 p0 = make_uint4(hx, f2tf32(v.x - __uint_as_float(hx)),
                                  hy, f2tf32(v.y - __uint_as_float(hy)));
            uint4 p1 = make_uint4(hz, f2tf32(v.z - __uint_as_float(hz)),
                                  hw, f2tf32(v.w - __uint_as_float(hw)));
            int kl = khalf + h * 4;
            *reinterpret_cast<uint4*>(&sA[mrow * KSTR + kl])     = p0;
            *reinterpret_cast<uint4*>(&sA[mrow * KSTR + kl + 2]) = p1;
            // ---- W ----
            float4 w = (gk < 64) ? wl4[mrow * 16 + (gk >> 2)]
                                 : wr4[mrow * 16 + ((gk - 64) >> 2)];
            uint32_t wx = f2tf32(w.x), wy = f2tf32(w.y), wz = f2tf32(w.z), ww = f2tf32(w.w);
            uint4 q0 = make_uint4(wx, f2tf32(w.x - __uint_as_float(wx)),
                                  wy, f2tf32(w.y - __uint_as_float(wy)));
            uint4 q1 = make_uint4(wz, f2tf32(w.z - __uint_as_float(wz)),
                                  ww, f2tf32(w.w - __uint_as_float(ww)));
            *reinterpret_cast<uint4*>(&sW[mrow * KSTR + kl])     = q0;
            *reinterpret_cast<uint4*>(&sW[mrow * KSTR + kl + 2]) = q1;
        }
        __syncthreads();

#pragma unroll
        for (int ks = 0; ks < 2; ks++) {
            int k8 = ks * 8;
            uint2 A0[2], A1[2], A2[2], A3[2];
#pragma unroll
            for (int mt = 0; mt < 2; mt++) {
                int rb = wm + mt * 16 + g;
                A0[mt] = sA[rb * KSTR + k8 + tg];
                A1[mt] = sA[(rb + 8) * KSTR + k8 + tg];
                A2[mt] = sA[rb * KSTR + k8 + tg + 4];
                A3[mt] = sA[(rb + 8) * KSTR + k8 + tg + 4];
            }
#pragma unroll
            for (int nt = 0; nt < 8; nt++) {
                int jb = wn + nt * 8 + g;
                uint2 B0 = sW[jb * KSTR + k8 + tg];
                uint2 B1 = sW[jb * KSTR + k8 + tg + 4];
#pragma unroll
                for (int mt = 0; mt < 2; mt++) {
                    MMA_TF32(c[mt][nt], A0[mt].x, A1[mt].x, A2[mt].x, A3[mt].x, B0.x, B1.x);
                    MMA_TF32(c[mt][nt], A0[mt].x, A1[mt].x, A2[mt].x, A3[mt].x, B0.y, B1.y);
                    MMA_TF32(c[mt][nt], A0[mt].y, A1[mt].y, A2[mt].y, A3[mt].y, B0.x, B1.x);
                }
            }
        }
    }

    // epilogue: h = relu(dot + b); fold rank-1; reduce over tig lanes; smem-atomic per row
#pragma unroll
    for (int mt = 0; mt < 2; mt++) {
#pragma unroll
        for (int half = 0; half < 2; half++) {
            int row = wm + mt * 16 + g + half * 8;
            float sp = 0.f, tp = 0.f;
#pragma unroll
            for (int nt = 0; nt < 8; nt++) {
#pragma unroll
                for (int e2 = 0; e2 < 2; e2++) {
                    int j = wn + nt * 8 + 2 * tg + e2;
                    float h = fmaxf(c[mt][nt][half * 2 + e2] + sb[j], 0.f);
                    sp = fmaf(h, s2l[j], sp);
                    tp = fmaf(h, s2r[j], tp);
                }
            }
            sp += __shfl_xor_sync(0xffffffffu, sp, 1);
            sp += __shfl_xor_sync(0xffffffffu, sp, 2);
            tp += __shfl_xor_sync(0xffffffffu, tp, 1);
            tp += __shfl_xor_sync(0xffffffffu, tp, 2);
            if (tg == 0) {
                atomicAdd(&sS[row], sp);
                atomicAdd(&sT[row], tp);
            }
        }
    }
    __syncthreads();
    if (tid < 128) {
        int n2 = nb + tid;
        if (n2 < N_NODES) { g_s[n2] = sS[tid]; g_t[n2] = sT[tid]; }
    }
}

// ---------------- K4 ----------------
__global__ __launch_bounds__(256) void k_gather2v(const float* __restrict__ b2l) {
    int i = blockIdx.x * blockDim.x + threadIdx.x;
    if (i >= N_NODES) return;
    int deg = g_cnt[i];
    int n = min(deg, CAP);
    const int* sl = g_slots + i * CAP;
    float acc = 0.f;
    for (int e = 0; e < n; e++) acc += g_s[sl[e]];
    float inv = 1.0f / fmaxf((float)deg, 1.0f);
    g_v[i] = fmaxf(fmaf(acc, inv, b2l[0] + g_t[i]), 0.f);
}

// ---------------- K5 ----------------
__global__ __launch_bounds__(256) void k_fc1(const float* __restrict__ fc1W) {
    int r     = blockIdx.x & (LAST_HID - 1);
    int split = blockIdx.x >> 8;
    const int chunk4 = (N_NODES / 4) / FC1_SPLIT;
    int base = split * chunk4;
    const float4* wp = reinterpret_cast<const float4*>(fc1W + (size_t)r * N_NODES) + base;
    const float4* vp = reinterpret_cast<const float4*>(g_v) + base;
    float acc = 0.f;
    for (int idx = threadIdx.x; idx < chunk4; idx += 256) {
        float4 w = wp[idx];
        float4 v = vp[idx];
        acc = fmaf(w.x, v.x, acc);
        acc = fmaf(w.y, v.y, acc);
        acc = fmaf(w.z, v.z, acc);
        acc = fmaf(w.w, v.w, acc);
    }
    __shared__ float red[256];
    red[threadIdx.x] = acc;
    __syncthreads();
#pragma unroll
    for (int off = 128; off > 0; off >>= 1) {
        if (threadIdx.x < off) red[threadIdx.x] += red[threadIdx.x + off];
        __syncthreads();
    }
    if (threadIdx.x == 0) atomicAdd(&g_z[r], red[0]);
}

// ---------------- K6 ----------------
__global__ __launch_bounds__(256) void k_final(const float* __restrict__ fc2W,
                                               const float* __restrict__ fc2b,
                                               float* __restrict__ out) {
    __shared__ float red[256];
    int tid = threadIdx.x;
    red[tid] = fc2W[tid] * g_z[tid];
    __syncthreads();
#pragma unroll
    for (int off = 128; off > 0; off >>= 1) {
        if (tid < off) red[tid] += red[tid + off];
        __syncthreads();
    }
    if (tid == 0) out[0] = red[0] + fc2b[0];
}

// ---------------- launch ----------------
extern "C" void kernel_launch(void* const* d_in, const int* in_sizes, int n_in,
                              void* d_out, int out_size) {
    const float* x    = (const float*)d_in[0];
    const void*  ei   = d_in[1];
    const float* W1l  = (const float*)d_in[2];
    const float* b1l  = (const float*)d_in[3];
    const float* W1r  = (const float*)d_in[4];
    const float* W2l  = (const float*)d_in[5];
    const float* b2l  = (const float*)d_in[6];
    const float* W2r  = (const float*)d_in[7];
    const float* fc1W = (const float*)d_in[8];
    const float* fc1b = (const float*)d_in[9];
    const float* fc2W = (const float*)d_in[10];
    const float* fc2b = (const float*)d_in[11];
    float* out = (float*)d_out;

    k_init<<<256, 256>>>((const int*)ei, fc1b);
    k_fill<<<(N_EDGES + 255) / 256, 256>>>(ei);
    k_gather1<<<(N_NODES * 16 + 255) / 256, 256>>>(x);
    k_layer1<<<NTILES_MMA, 256>>>(x, W1l, b1l, W1r, W2l, W2r);
    k_gather2v<<<(N_NODES + 255) / 256, 256>>>(b2l);
    k_fc1<<<LAST_HID * FC1_SPLIT, 256>>>(fc1W);
    k_final<<<1, 256>>>(fc2W, fc2b, out);
}